// round 14
// baseline (speedup 1.0000x reference)
#include <cuda_runtime.h>
#include <cstdint>

#define BATCH  4
#define DMODEL 1024
#define NSTATE 64
#define LSEQ   2048
#define LHALF  1024
#define MROWS  1152   // 1024 (Delta) + 64 (Bm) + 64 (Cm)

// ---------------- device scratch (allocation-free) ----------------
__device__ __align__(256) float g_W[MROWS * DMODEL];                 // tf32-rounded [Delta; Bm; Cm]
__device__ __align__(256) float g_U[(size_t)BATCH * DMODEL * LSEQ];  // tf32-rounded u (GEMM only)
__device__ __align__(256) float g_S[(size_t)BATCH * MROWS * LSEQ];   // [delta; Bu; Cu] per batch
__device__ __align__(256) float g_H[(size_t)BATCH * DMODEL * NSTATE];// h* = state after l=1023
__device__ __align__(256) float g_G[(size_t)BATCH * DMODEL * LHALF]; // cumprod(delta), 2nd half
__device__ __align__(256) float g_P[NSTATE * LHALF];                 // A_n^(m+1), [n][m]

// ---------------- f32x2 packed helpers ----------------
__device__ __forceinline__ uint64_t dup2(float x) {
    uint64_t r; asm("mov.b64 %0, {%1, %1};" : "=l"(r) : "f"(x)); return r;
}
__device__ __forceinline__ uint64_t mul2(uint64_t a, uint64_t b) {
    uint64_t r; asm("mul.rn.f32x2 %0, %1, %2;" : "=l"(r) : "l"(a), "l"(b)); return r;
}
__device__ __forceinline__ uint64_t fma2(uint64_t a, uint64_t b, uint64_t c) {
    uint64_t r; asm("fma.rn.f32x2 %0, %1, %2, %3;" : "=l"(r) : "l"(a), "l"(b), "l"(c)); return r;
}
__device__ __forceinline__ float2 u64_f2(uint64_t v) {
    float2 f; asm("mov.b64 {%0, %1}, %2;" : "=f"(f.x), "=f"(f.y) : "l"(v)); return f;
}

// ---------------- tf32 helpers ----------------
__device__ __forceinline__ float tf32r(float x) {
    uint32_t r; asm("cvt.rna.tf32.f32 %0, %1;" : "=r"(r) : "f"(x));
    return __uint_as_float(r);
}
__device__ __forceinline__ void mma_tf32(float* c, const uint32_t* a, const uint32_t* b) {
    asm volatile("mma.sync.aligned.m16n8k8.row.col.f32.tf32.tf32.f32 "
        "{%0,%1,%2,%3}, {%4,%5,%6,%7}, {%8,%9}, {%0,%1,%2,%3};"
        : "+f"(c[0]), "+f"(c[1]), "+f"(c[2]), "+f"(c[3])
        : "r"(a[0]), "r"(a[1]), "r"(a[2]), "r"(a[3]), "r"(b[0]), "r"(b[1]));
}
__device__ __forceinline__ void cpasync16(uint32_t dst, const void* src) {
    asm volatile("cp.async.cg.shared.global [%0], [%1], 16;" :: "r"(dst), "l"(src) : "memory");
}
__device__ __forceinline__ uint32_t smem_u32(const void* p) {
    uint32_t a;
    asm("{ .reg .u64 t; cvta.to.shared.u64 t, %1; cvt.u32.u64 %0, t; }" : "=r"(a) : "l"(p));
    return a;
}
#define CP_COMMIT() asm volatile("cp.async.commit_group;" ::: "memory")

// ---------------- kernel 0: pack + tf32-round W ----------------
__global__ __launch_bounds__(256) void pack_w_kernel(
    const float* __restrict__ Delta, const float* __restrict__ Bm, const float* __restrict__ Cm)
{
    int i = blockIdx.x * 256 + threadIdx.x;
    if (i >= MROWS * DMODEL) return;
    int r = i >> 10, c = i & 1023;
    float v;
    if (r < 1024)      v = Delta[r * DMODEL + c];
    else if (r < 1088) v = Bm[(r - 1024) * DMODEL + c];
    else               v = Cm[(r - 1088) * DMODEL + c];
    g_W[i] = tf32r(v);
}

// ---------------- kernel 0b: tf32-round u -> g_U ----------------
__global__ __launch_bounds__(256) void round_u_kernel(const float* __restrict__ u)
{
    size_t i = (size_t)blockIdx.x * 256 + threadIdx.x;
    float4 v = ((const float4*)u)[i];
    v.x = tf32r(v.x); v.y = tf32r(v.y); v.z = tf32r(v.z); v.w = tf32r(v.w);
    ((float4*)g_U)[i] = v;
}

// ---------------- kernel 0c: A-power table  g_P[n][m] = min(A_n^(m+1), 1e30) ----------------
__global__ __launch_bounds__(256) void apow_kernel(const float* __restrict__ A)
{
    int i = blockIdx.x * 256 + threadIdx.x;
    int n = i >> 10, m = i & 1023;
    float lg = log2f(A[n]);
    float v  = exp2f((float)(m + 1) * lg);
    g_P[n * LHALF + m] = fminf(v, 1e30f);
}

// ---------------- kernel 1: tf32 mma.sync GEMM  g_S[b] = g_W @ g_U[b] ----------------
#define BM 128
#define BN 128
#define BK 32
#define ASTR 36
#define BSTR 136
#define AF (BM * ASTR)
#define BF (BK * BSTR)
#define STF (AF + BF)
#define SMEM_G (2 * STF * 4)
#define NCHUNK (DMODEL / BK)

__device__ __forceinline__ void load_chunk_g(int tid, int c, int m0, int n0,
                                             const float* __restrict__ Ub,
                                             uint32_t aSm, uint32_t bSm)
{
    const float* Wt = g_W + (size_t)m0 * DMODEL + c * BK;
#pragma unroll
    for (int i = 0; i < 4; i++) {
        int t = tid + 256 * i;
        int r = t >> 3, j = t & 7;
        cpasync16(aSm + r * (ASTR * 4) + j * 16, Wt + (size_t)r * DMODEL + j * 4);
    }
    const float* Ut = Ub + (size_t)(c * BK) * LSEQ + n0;
#pragma unroll
    for (int i = 0; i < 4; i++) {
        int t = tid + 256 * i;
        int k = t >> 5, j = t & 31;
        cpasync16(bSm + k * (BSTR * 4) + j * 16, Ut + (size_t)k * LSEQ + j * 4);
    }
}

__global__ __launch_bounds__(256, 2) void gemm_mma_kernel()
{
    extern __shared__ __align__(16) float sm[];
    const int tid  = threadIdx.x;
    const int wid  = tid >> 5, lane = tid & 31;
    const int wm   = wid & 3, wn = wid >> 2;
    const int g    = lane >> 2, tg = lane & 3;

    const int b  = blockIdx.z;
    const int m0 = blockIdx.y * BM;
    const int n0 = blockIdx.x * BN;
    const float* __restrict__ Ub = g_U + (size_t)b * DMODEL * LSEQ;
    float* __restrict__ Cb = g_S + (size_t)b * MROWS * LSEQ;

    const uint32_t sb = smem_u32(sm);
    const uint32_t aSm[2] = {sb, sb + STF * 4};
    const uint32_t bSm[2] = {sb + AF * 4, sb + STF * 4 + AF * 4};
    const uint32_t* aP[2] = {(const uint32_t*)sm, (const uint32_t*)(sm + STF)};
    const uint32_t* bP[2] = {(const uint32_t*)(sm + AF), (const uint32_t*)(sm + STF + AF)};

    float acc[2][8][4];
#pragma unroll
    for (int mt = 0; mt < 2; mt++)
#pragma unroll
        for (int nt = 0; nt < 8; nt++)
#pragma unroll
            for (int q = 0; q < 4; q++) acc[mt][nt][q] = 0.f;

    load_chunk_g(tid, 0, m0, n0, Ub, aSm[0], bSm[0]);
    CP_COMMIT();

    for (int c = 0; c < NCHUNK; c++) {
        const int s = c & 1;
        if (c + 1 < NCHUNK) {
            load_chunk_g(tid, c + 1, m0, n0, Ub, aSm[1 - s], bSm[1 - s]);
            CP_COMMIT();
            asm volatile("cp.async.wait_group 1;" ::: "memory");
        } else {
            asm volatile("cp.async.wait_group 0;" ::: "memory");
        }
        __syncthreads();

        const uint32_t* As = aP[s];
        const uint32_t* Bs = bP[s];
#pragma unroll
        for (int ks = 0; ks < 4; ks++) {
            const int k0 = ks * 8;
            uint32_t af[2][4];
#pragma unroll
            for (int mt = 0; mt < 2; mt++) {
                int row = wm * 32 + mt * 16;
                af[mt][0] = As[(row + g)     * ASTR + k0 + tg];
                af[mt][1] = As[(row + g + 8) * ASTR + k0 + tg];
                af[mt][2] = As[(row + g)     * ASTR + k0 + tg + 4];
                af[mt][3] = As[(row + g + 8) * ASTR + k0 + tg + 4];
            }
            uint32_t bf[8][2];
#pragma unroll
            for (int nt = 0; nt < 8; nt++) {
                int col = wn * 64 + nt * 8 + g;
                bf[nt][0] = Bs[(k0 + tg)     * BSTR + col];
                bf[nt][1] = Bs[(k0 + tg + 4) * BSTR + col];
            }
#pragma unroll
            for (int mt = 0; mt < 2; mt++)
#pragma unroll
                for (int nt = 0; nt < 8; nt++)
                    mma_tf32(acc[mt][nt], af[mt], bf[nt]);
        }
        __syncthreads();
    }

#pragma unroll
    for (int mt = 0; mt < 2; mt++) {
        int row0 = m0 + wm * 32 + mt * 16 + g;
#pragma unroll
        for (int nt = 0; nt < 8; nt++) {
            int col = n0 + wn * 64 + nt * 8 + 2 * tg;
            float2 v0 = {acc[mt][nt][0], acc[mt][nt][1]};
            float2 v1 = {acc[mt][nt][2], acc[mt][nt][3]};
            *(float2*)(Cb + (size_t)row0 * LSEQ + col)       = v0;
            *(float2*)(Cb + (size_t)(row0 + 8) * LSEQ + col) = v1;
        }
    }
}

// ---------------- kernel 2: half-scan, 1-wave occupancy (4 CTAs/SM) ----------------
// 256 thr = 32 d x 8 c, 8 n/thread. grid (32, BATCH, 2) = 512 blocks.
// sYp shrunk to 16 l-rows (two body/writeback phases per 32-l tile) so
// smem = 47.6 KB -> 4 CTAs/SM -> 592 slots >= 512 blocks = ONE wave.
#define DT  32
#define TL  32
#define YPL 16
#define SBS 66
#define SDS 36
// dynamic smem layout (floats)
#define OF_BU 0
#define OF_CU (OF_BU + TL * SBS)            // 2112
#define OF_DE (OF_CU + TL * SBS)            // 4224
#define OF_U  (OF_DE + DT * SDS)            // 5376
#define OF_YP (OF_U  + DT * SDS)            // 6528
#define OF_G  (OF_YP + YPL * 256)           // 10624
#define SCAN_FLOATS (OF_G + DT * 40)        // 11904
#define SMEM_SCAN (SCAN_FLOATS * 4)         // 47616 bytes

__global__ __launch_bounds__(256, 4) void scan_half_kernel(
    const float* __restrict__ u, const float* __restrict__ A,
    const float* __restrict__ Dv, float* __restrict__ y)
{
    extern __shared__ __align__(16) float sw[];
    float* sBu = sw + OF_BU;
    float* sCu = sw + OF_CU;
    float* sDe = sw + OF_DE;
    float* sU  = sw + OF_U;
    float* sYp = sw + OF_YP;
    float* sG  = sw + OF_G;

    const int b    = blockIdx.y;
    const int d0   = blockIdx.x * DT;
    const int half = blockIdx.z;
    const int lbase = half * LHALF;
    const bool wantG = (half == 1);

    const float* __restrict__ de = g_S + (size_t)b * MROWS * LSEQ;
    const float* __restrict__ Bu = de + (size_t)1024 * LSEQ;
    const float* __restrict__ Cu = de + (size_t)1088 * LSEQ;
    const float* __restrict__ ub = u + (size_t)b * DMODEL * LSEQ;

    const int tid = threadIdx.x;
    const int dl  = tid >> 3;    // 0..31
    const int c   = tid & 7;     // 0..7
    const int n0  = c * 8;

    uint64_t A2[4];
#pragma unroll
    for (int p = 0; p < 4; p++)
        A2[p] = *(const uint64_t*)&A[n0 + 2 * p];

    uint64_t h2[4] = {0ull, 0ull, 0ull, 0ull};
    float g = 1.0f;

    for (int lt = 0; lt < LHALF; lt += TL) {
        const int l0 = lbase + lt;

        // Bu/Cu tile: 64 n x 32 l, transposed to [l][n]
#pragma unroll
        for (int t = 0; t < 2; t++) {
            int f4 = tid + 256 * t;
            int n  = f4 >> 3;
            int q  = f4 & 7;
            float4 v = *(const float4*)(Bu + (size_t)n * LSEQ + l0 + q * 4);
            sBu[(q * 4 + 0) * SBS + n] = v.x; sBu[(q * 4 + 1) * SBS + n] = v.y;
            sBu[(q * 4 + 2) * SBS + n] = v.z; sBu[(q * 4 + 3) * SBS + n] = v.w;
            float4 w = *(const float4*)(Cu + (size_t)n * LSEQ + l0 + q * 4);
            sCu[(q * 4 + 0) * SBS + n] = w.x; sCu[(q * 4 + 1) * SBS + n] = w.y;
            sCu[(q * 4 + 2) * SBS + n] = w.z; sCu[(q * 4 + 3) * SBS + n] = w.w;
        }
        // delta / u tiles: 32 d x 32 l
        {
            int dd = tid >> 3, q = tid & 7;
            *(float4*)&sDe[dd * SDS + q * 4] =
                *(const float4*)(de + (size_t)(d0 + dd) * LSEQ + l0 + q * 4);
            *(float4*)&sU[dd * SDS + q * 4] =
                *(const float4*)(ub + (size_t)(d0 + dd) * LSEQ + l0 + q * 4);
        }
        __syncthreads();

#pragma unroll
        for (int ph = 0; ph < 2; ph++) {
            const int lb0 = ph * YPL;
#pragma unroll 8
            for (int li = 0; li < YPL; li++) {
                const int l = lb0 + li;
                float ds = sDe[dl * SDS + l];
                float us = sU[dl * SDS + l];
                float du = ds * us;
                if (wantG) {
                    g *= ds;
                    if (c == 0) sG[dl * 40 + l] = g;
                }
                uint64_t d2  = dup2(ds);
                uint64_t du2 = dup2(du);
                uint64_t y2  = 0ull;
                const uint64_t* bup = (const uint64_t*)&sBu[l * SBS + n0];
                const uint64_t* cup = (const uint64_t*)&sCu[l * SBS + n0];
#pragma unroll
                for (int p = 0; p < 4; p++) {
                    uint64_t dA = mul2(d2, A2[p]);
                    uint64_t pb = mul2(du2, bup[p]);
                    h2[p] = fma2(dA, h2[p], pb);
                    y2    = fma2(cup[p], h2[p], y2);
                }
                float2 yf = u64_f2(y2);
                sYp[li * 256 + dl * 8 + c] = yf.x + yf.y;
            }
            __syncthreads();

            // writeback 16 l: thread (dd, q) handles l = lb0 + q*2 + {0,1}
            {
                int dd = tid >> 3, q = tid & 7;
                int lw = lb0 + q * 2;
                float2 uv = *(const float2*)&sU[dd * SDS + lw];
                float2 o;
#pragma unroll
                for (int i = 0; i < 2; i++) {
                    int li = q * 2 + i;
                    const float4* pp = (const float4*)&sYp[li * 256 + dd * 8];
                    float4 p0 = pp[0], p1 = pp[1];
                    (&o.x)[i] = ((p0.x + p0.y) + (p0.z + p0.w)) +
                                ((p1.x + p1.y) + (p1.z + p1.w));
                }
                float Ddw = Dv[d0 + dd];
                o.x += uv.x * Ddw;
                o.y += uv.y * Ddw;
                *(float2*)(y + ((size_t)b * DMODEL + d0 + dd) * LSEQ + l0 + lw) = o;

                if (wantG) {
                    float2 gv = *(const float2*)&sG[dd * 40 + lw];
                    *(float2*)(g_G + ((size_t)b * DMODEL + d0 + dd) * LHALF + lt + lw) = gv;
                }
            }
            __syncthreads();
        }
    }

    if (half == 0) {
        float* hp = g_H + ((size_t)b * DMODEL + d0 + dl) * NSTATE + n0;
#pragma unroll
        for (int p = 0; p < 4; p++) {
            float2 v = u64_f2(h2[p]);
            *(float2*)(hp + 2 * p) = v;
        }
    }
}

// ---------------- kernel 3: second-half correction ----------------
// y[b,d,1024+l] += g_G[b,d,l] * sum_n (Cu[n,1024+l] * A_n^(l+1)) * h*[b,d,n]
#define CD 128
#define CL 128
#define HSTR 68
#define VSTR 132
#define SMEM_CORR ((CD * HSTR + NSTATE * VSTR) * 4)   // 68608

__global__ __launch_bounds__(256) void corr_kernel(float* __restrict__ y)
{
    extern __shared__ __align__(16) float cs[];
    float* Hs = cs;                  // [CD][HSTR]
    float* Vs = cs + CD * HSTR;      // [NSTATE][VSTR]

    const int b   = blockIdx.z;
    const int dd0 = blockIdx.y * CD;
    const int ll0 = blockIdx.x * CL;
    const int tid = threadIdx.x;
    const int tl  = tid & 15;
    const int td  = tid >> 4;

    const float* Hg = g_H + ((size_t)b * DMODEL + dd0) * NSTATE;
    for (int i = tid; i < (CD * NSTATE) / 4; i += 256) {
        int dd = i >> 4, nn4 = (i & 15) * 4;
        *(float4*)&Hs[dd * HSTR + nn4] = *(const float4*)(Hg + dd * NSTATE + nn4);
    }
    const float* CuG = g_S + (size_t)b * MROWS * LSEQ + (size_t)1088 * LSEQ + LHALF + ll0;
    for (int i = tid; i < (NSTATE * CL) / 4; i += 256) {
        int nn = i >> 5, ll4 = (i & 31) * 4;
        float4 cu = *(const float4*)(CuG + (size_t)nn * LSEQ + ll4);
        float4 ap = *(const float4*)(g_P + nn * LHALF + ll0 + ll4);
        float4 v = {cu.x * ap.x, cu.y * ap.y, cu.z * ap.z, cu.w * ap.w};
        *(float4*)&Vs[nn * VSTR + ll4] = v;
    }
    __syncthreads();

    uint64_t acc[8][4];
#pragma unroll
    for (int i = 0; i < 8; i++)
#pragma unroll
        for (int j = 0; j < 4; j++) acc[i][j] = 0ull;

#pragma unroll 8
    for (int k = 0; k < NSTATE; k++) {
        ulonglong2 b0 = *(const ulonglong2*)&Vs[k * VSTR + tl * 8];
        ulonglong2 b1 = *(const ulonglong2*)&Vs[k * VSTR + tl * 8 + 4];
#pragma unroll
        for (int i = 0; i < 8; i++) {
            uint64_t ai = dup2(Hs[(td * 8 + i) * HSTR + k]);
            acc[i][0] = fma2(ai, b0.x, acc[i][0]);
            acc[i][1] = fma2(ai, b0.y, acc[i][1]);
            acc[i][2] = fma2(ai, b1.x, acc[i][2]);
            acc[i][3] = fma2(ai, b1.y, acc[i][3]);
        }
    }

#pragma unroll
    for (int i = 0; i < 8; i++) {
        int d = dd0 + td * 8 + i;
        const float* gp = g_G + ((size_t)b * DMODEL + d) * LHALF + ll0 + tl * 8;
        float* yp = y + ((size_t)b * DMODEL + d) * LSEQ + LHALF + ll0 + tl * 8;
        float4 g0 = *(const float4*)gp;
        float4 g1 = *(const float4*)(gp + 4);
        float4 y0 = *(const float4*)yp;
        float4 y1 = *(const float4*)(yp + 4);
        float2 a0 = u64_f2(acc[i][0]), a1 = u64_f2(acc[i][1]);
        float2 a2 = u64_f2(acc[i][2]), a3 = u64_f2(acc[i][3]);
        y0.x += g0.x * a0.x; y0.y += g0.y * a0.y;
        y0.z += g0.z * a1.x; y0.w += g0.w * a1.y;
        y1.x += g1.x * a2.x; y1.y += g1.y * a2.y;
        y1.z += g1.z * a3.x; y1.w += g1.w * a3.y;
        *(float4*)yp       = y0;
        *(float4*)(yp + 4) = y1;
    }
}

// ---------------- host launcher ----------------
extern "C" void kernel_launch(void* const* d_in, const int* in_sizes, int n_in,
                              void* d_out, int out_size)
{
    const float* u  = nullptr;
    const float* A  = nullptr;
    const float* Bm = nullptr;
    const float* Cm = nullptr;
    const float* D  = nullptr;
    const float* De = nullptr;
    for (int i = 0; i < n_in; i++) {
        int s = in_sizes[i];
        const float* p = (const float*)d_in[i];
        if      (s == 8388608 && !u)  u  = p;
        else if (s == 64      && !A)  A  = p;
        else if (s == 65536) { if (!Bm) Bm = p; else if (!Cm) Cm = p; }
        else if (s == 1024    && !D)  D  = p;
        else if (s == 1048576 && !De) De = p;
    }
    float* y = (float*)d_out;
    (void)out_size;

    cudaFuncSetAttribute(gemm_mma_kernel,
                         cudaFuncAttributeMaxDynamicSharedMemorySize, SMEM_G);
    cudaFuncSetAttribute(scan_half_kernel,
                         cudaFuncAttributeMaxDynamicSharedMemorySize, SMEM_SCAN);
    cudaFuncSetAttribute(corr_kernel,
                         cudaFuncAttributeMaxDynamicSharedMemorySize, SMEM_CORR);

    // 0) pack + round W; round u; A-power table
    pack_w_kernel<<<(MROWS * DMODEL + 255) / 256, 256>>>(De, Bm, Cm);
    round_u_kernel<<<(BATCH * DMODEL * LSEQ / 4 + 255) / 256, 256>>>(u);
    apow_kernel<<<(NSTATE * LHALF + 255) / 256, 256>>>(A);

    // 1) tf32 mma.sync GEMM: g_S[b] = W @ u[b]
    {
        dim3 grid(LSEQ / BN, MROWS / BM, BATCH);   // 16 x 9 x 4
        gemm_mma_kernel<<<grid, 256, SMEM_G>>>();
    }
    // 2) both halves scanned in parallel (single wave @ 4 CTAs/SM)
    {
        dim3 grid(DMODEL / DT, BATCH, 2);          // 32 x 4 x 2 = 256 blocks... x2 halves = 512 total
        scan_half_kernel<<<grid, 256, SMEM_SCAN>>>(u, A, D, y);
    }
    // 3) second-half correction
    {
        dim3 grid(LHALF / CL, DMODEL / CD, BATCH); // 8 x 8 x 4 = 256 blocks
        corr_kernel<<<grid, 256, SMEM_CORR>>>(y);
    }
}

// round 15
// speedup vs baseline: 1.3209x; 1.3209x over previous
#include <cuda_runtime.h>
#include <cstdint>

#define BATCH  4
#define DMODEL 1024
#define NSTATE 64
#define LSEQ   2048
#define NCH    4
#define CHL    (LSEQ / NCH)     // 512
#define MROWS  1152             // 1024 (Delta) + 64 (Bm) + 64 (Cm)
#define APOWL  1024

// ---------------- device scratch (allocation-free) ----------------
__device__ __align__(256) float g_W[MROWS * DMODEL];
__device__ __align__(256) float g_U[(size_t)BATCH * DMODEL * LSEQ];
__device__ __align__(256) float g_S[(size_t)BATCH * MROWS * LSEQ];
__device__ __align__(256) float g_G[(size_t)BATCH * DMODEL * LSEQ];    // within-chunk cumprod(delta)
__device__ __align__(256) float g_H [(size_t)BATCH * NCH * DMODEL * NSTATE]; // h* per chunk (end state)
__device__ __align__(256) float g_H2[(size_t)BATCH * NCH * DMODEL * NSTATE]; // hstart per chunk
__device__ __align__(256) float g_P[NSTATE * APOWL];                   // A_n^(m+1)

// ---------------- f32x2 packed helpers ----------------
__device__ __forceinline__ uint64_t dup2(float x) {
    uint64_t r; asm("mov.b64 %0, {%1, %1};" : "=l"(r) : "f"(x)); return r;
}
__device__ __forceinline__ uint64_t mul2(uint64_t a, uint64_t b) {
    uint64_t r; asm("mul.rn.f32x2 %0, %1, %2;" : "=l"(r) : "l"(a), "l"(b)); return r;
}
__device__ __forceinline__ uint64_t fma2(uint64_t a, uint64_t b, uint64_t c) {
    uint64_t r; asm("fma.rn.f32x2 %0, %1, %2, %3;" : "=l"(r) : "l"(a), "l"(b), "l"(c)); return r;
}
__device__ __forceinline__ float2 u64_f2(uint64_t v) {
    float2 f; asm("mov.b64 {%0, %1}, %2;" : "=f"(f.x), "=f"(f.y) : "l"(v)); return f;
}

// ---------------- tf32 helpers ----------------
__device__ __forceinline__ float tf32r(float x) {
    uint32_t r; asm("cvt.rna.tf32.f32 %0, %1;" : "=r"(r) : "f"(x));
    return __uint_as_float(r);
}
__device__ __forceinline__ void mma_tf32(float* c, const uint32_t* a, const uint32_t* b) {
    asm volatile("mma.sync.aligned.m16n8k8.row.col.f32.tf32.tf32.f32 "
        "{%0,%1,%2,%3}, {%4,%5,%6,%7}, {%8,%9}, {%0,%1,%2,%3};"
        : "+f"(c[0]), "+f"(c[1]), "+f"(c[2]), "+f"(c[3])
        : "r"(a[0]), "r"(a[1]), "r"(a[2]), "r"(a[3]), "r"(b[0]), "r"(b[1]));
}
__device__ __forceinline__ void cpasync16(uint32_t dst, const void* src) {
    asm volatile("cp.async.cg.shared.global [%0], [%1], 16;" :: "r"(dst), "l"(src) : "memory");
}
__device__ __forceinline__ uint32_t smem_u32(const void* p) {
    uint32_t a;
    asm("{ .reg .u64 t; cvta.to.shared.u64 t, %1; cvt.u32.u64 %0, t; }" : "=r"(a) : "l"(p));
    return a;
}
#define CP_COMMIT() asm volatile("cp.async.commit_group;" ::: "memory")

// ---------------- kernel 0: pack + tf32-round W ----------------
__global__ __launch_bounds__(256) void pack_w_kernel(
    const float* __restrict__ Delta, const float* __restrict__ Bm, const float* __restrict__ Cm)
{
    int i = blockIdx.x * 256 + threadIdx.x;
    if (i >= MROWS * DMODEL) return;
    int r = i >> 10, c = i & 1023;
    float v;
    if (r < 1024)      v = Delta[r * DMODEL + c];
    else if (r < 1088) v = Bm[(r - 1024) * DMODEL + c];
    else               v = Cm[(r - 1088) * DMODEL + c];
    g_W[i] = tf32r(v);
}

// ---------------- kernel 0b: tf32-round u ----------------
__global__ __launch_bounds__(256) void round_u_kernel(const float* __restrict__ u)
{
    size_t i = (size_t)blockIdx.x * 256 + threadIdx.x;
    float4 v = ((const float4*)u)[i];
    v.x = tf32r(v.x); v.y = tf32r(v.y); v.z = tf32r(v.z); v.w = tf32r(v.w);
    ((float4*)g_U)[i] = v;
}

// ---------------- kernel 0c: A-power table  g_P[n][m] = min(A_n^(m+1), 1e30) ----------------
__global__ __launch_bounds__(256) void apow_kernel(const float* __restrict__ A)
{
    int i = blockIdx.x * 256 + threadIdx.x;
    int n = i >> 10, m = i & 1023;
    float lg = log2f(A[n]);
    float v  = exp2f((float)(m + 1) * lg);
    g_P[n * APOWL + m] = fminf(v, 1e30f);
}

// ---------------- kernel 1: tf32 mma.sync GEMM (unchanged, known-good) ----------------
#define BM 128
#define BN 128
#define BK 32
#define ASTR 36
#define BSTR 136
#define AF (BM * ASTR)
#define BF (BK * BSTR)
#define STF (AF + BF)
#define SMEM_G (2 * STF * 4)
#define NCHUNK_G (DMODEL / BK)

__device__ __forceinline__ void load_chunk_g(int tid, int c, int m0, int n0,
                                             const float* __restrict__ Ub,
                                             uint32_t aSm, uint32_t bSm)
{
    const float* Wt = g_W + (size_t)m0 * DMODEL + c * BK;
#pragma unroll
    for (int i = 0; i < 4; i++) {
        int t = tid + 256 * i;
        int r = t >> 3, j = t & 7;
        cpasync16(aSm + r * (ASTR * 4) + j * 16, Wt + (size_t)r * DMODEL + j * 4);
    }
    const float* Ut = Ub + (size_t)(c * BK) * LSEQ + n0;
#pragma unroll
    for (int i = 0; i < 4; i++) {
        int t = tid + 256 * i;
        int k = t >> 5, j = t & 31;
        cpasync16(bSm + k * (BSTR * 4) + j * 16, Ut + (size_t)k * LSEQ + j * 4);
    }
}

__global__ __launch_bounds__(256, 2) void gemm_mma_kernel()
{
    extern __shared__ __align__(16) float sm[];
    const int tid  = threadIdx.x;
    const int wid  = tid >> 5, lane = tid & 31;
    const int wm   = wid & 3, wn = wid >> 2;
    const int g    = lane >> 2, tg = lane & 3;

    const int b  = blockIdx.z;
    const int m0 = blockIdx.y * BM;
    const int n0 = blockIdx.x * BN;
    const float* __restrict__ Ub = g_U + (size_t)b * DMODEL * LSEQ;
    float* __restrict__ Cb = g_S + (size_t)b * MROWS * LSEQ;

    const uint32_t sb = smem_u32(sm);
    const uint32_t aSm[2] = {sb, sb + STF * 4};
    const uint32_t bSm[2] = {sb + AF * 4, sb + STF * 4 + AF * 4};
    const uint32_t* aP[2] = {(const uint32_t*)sm, (const uint32_t*)(sm + STF)};
    const uint32_t* bP[2] = {(const uint32_t*)(sm + AF), (const uint32_t*)(sm + STF + AF)};

    float acc[2][8][4];
#pragma unroll
    for (int mt = 0; mt < 2; mt++)
#pragma unroll
        for (int nt = 0; nt < 8; nt++)
#pragma unroll
            for (int q = 0; q < 4; q++) acc[mt][nt][q] = 0.f;

    load_chunk_g(tid, 0, m0, n0, Ub, aSm[0], bSm[0]);
    CP_COMMIT();

    for (int c = 0; c < NCHUNK_G; c++) {
        const int s = c & 1;
        if (c + 1 < NCHUNK_G) {
            load_chunk_g(tid, c + 1, m0, n0, Ub, aSm[1 - s], bSm[1 - s]);
            CP_COMMIT();
            asm volatile("cp.async.wait_group 1;" ::: "memory");
        } else {
            asm volatile("cp.async.wait_group 0;" ::: "memory");
        }
        __syncthreads();

        const uint32_t* As = aP[s];
        const uint32_t* Bs = bP[s];
#pragma unroll
        for (int ks = 0; ks < 4; ks++) {
            const int k0 = ks * 8;
            uint32_t af[2][4];
#pragma unroll
            for (int mt = 0; mt < 2; mt++) {
                int row = wm * 32 + mt * 16;
                af[mt][0] = As[(row + g)     * ASTR + k0 + tg];
                af[mt][1] = As[(row + g + 8) * ASTR + k0 + tg];
                af[mt][2] = As[(row + g)     * ASTR + k0 + tg + 4];
                af[mt][3] = As[(row + g + 8) * ASTR + k0 + tg + 4];
            }
            uint32_t bf[8][2];
#pragma unroll
            for (int nt = 0; nt < 8; nt++) {
                int col = wn * 64 + nt * 8 + g;
                bf[nt][0] = Bs[(k0 + tg)     * BSTR + col];
                bf[nt][1] = Bs[(k0 + tg + 4) * BSTR + col];
            }
#pragma unroll
            for (int mt = 0; mt < 2; mt++)
#pragma unroll
                for (int nt = 0; nt < 8; nt++)
                    mma_tf32(acc[mt][nt], af[mt], bf[nt]);
        }
        __syncthreads();
    }

#pragma unroll
    for (int mt = 0; mt < 2; mt++) {
        int row0 = m0 + wm * 32 + mt * 16 + g;
#pragma unroll
        for (int nt = 0; nt < 8; nt++) {
            int col = n0 + wn * 64 + nt * 8 + 2 * tg;
            float2 v0 = {acc[mt][nt][0], acc[mt][nt][1]};
            float2 v1 = {acc[mt][nt][2], acc[mt][nt][3]};
            *(float2*)(Cb + (size_t)row0 * LSEQ + col)       = v0;
            *(float2*)(Cb + (size_t)(row0 + 8) * LSEQ + col) = v1;
        }
    }
}

// ---------------- kernel 2: quarter-scan, 4 d per thread ----------------
// 256 thr = 16 dl x 16 c; thread owns n0=c*4 for d = d0+dl+{0,16,32,48}.
// Grid (16, 4, 4) = 256 blocks. 20 smem-bytes per d-step (vs 44 in r11).
#define DT  64      // d per block
#define TL  32      // l per tile
#define SBS 68      // Bu/Cu row stride (16B-aligned LDS.128: 272l+16c)
#define SDS 36
// smem layout (floats)
#define OF_BU 0
#define OF_CU (OF_BU + TL * SBS)             // 2176
#define OF_DE (OF_CU + TL * SBS)             // 4352
#define OF_U  (OF_DE + DT * SDS)             // 6656
#define OF_G  (OF_U  + DT * SDS)             // 8960
#define OF_YP (OF_G  + DT * SDS)             // 11264
#define SCAN_FLOATS (OF_YP + 16 * 1024)      // 27648
#define SMEM_SCAN (SCAN_FLOATS * 4)          // 110592 bytes -> 2 CTAs/SM

__global__ __launch_bounds__(256, 2) void scan_q_kernel(
    const float* __restrict__ u, const float* __restrict__ A,
    const float* __restrict__ Dv, float* __restrict__ y)
{
    extern __shared__ __align__(16) float sw[];
    float* sBu = sw + OF_BU;
    float* sCu = sw + OF_CU;
    float* sDe = sw + OF_DE;
    float* sU  = sw + OF_U;
    float* sG  = sw + OF_G;
    float* sYp = sw + OF_YP;    // [16 l][1024 = 64 d x 16 c]

    const int b     = blockIdx.y;
    const int d0    = blockIdx.x * DT;
    const int chunk = blockIdx.z;
    const int lbase = chunk * CHL;
    const bool wantG = (chunk > 0);
    const bool wantH = (chunk < NCH - 1);

    const float* __restrict__ de = g_S + (size_t)b * MROWS * LSEQ;
    const float* __restrict__ Bu = de + (size_t)1024 * LSEQ;
    const float* __restrict__ Cu = de + (size_t)1088 * LSEQ;
    const float* __restrict__ ub = u + (size_t)b * DMODEL * LSEQ;

    const int tid = threadIdx.x;
    const int dl  = tid >> 4;    // 0..15
    const int c   = tid & 15;    // 0..15
    const int n0  = c * 4;

    uint64_t A2[2];
#pragma unroll
    for (int p = 0; p < 2; p++)
        A2[p] = *(const uint64_t*)&A[n0 + 2 * p];

    const float Ddw = Dv[d0 + (tid >> 2)];   // for writeback role (dd = tid>>2)

    uint64_t h[4][2];
#pragma unroll
    for (int k = 0; k < 4; k++) { h[k][0] = 0ull; h[k][1] = 0ull; }
    float g[4] = {1.f, 1.f, 1.f, 1.f};

    for (int lt = 0; lt < CHL; lt += TL) {
        const int l0 = lbase + lt;
        __syncthreads();

        // stage Bu/Cu: 64 n x 32 l -> [l][n]
#pragma unroll
        for (int t = 0; t < 2; t++) {
            int f4 = tid + 256 * t;
            int n  = f4 >> 3;
            int q  = f4 & 7;
            float4 v = *(const float4*)(Bu + (size_t)n * LSEQ + l0 + q * 4);
            sBu[(q * 4 + 0) * SBS + n] = v.x; sBu[(q * 4 + 1) * SBS + n] = v.y;
            sBu[(q * 4 + 2) * SBS + n] = v.z; sBu[(q * 4 + 3) * SBS + n] = v.w;
            float4 w = *(const float4*)(Cu + (size_t)n * LSEQ + l0 + q * 4);
            sCu[(q * 4 + 0) * SBS + n] = w.x; sCu[(q * 4 + 1) * SBS + n] = w.y;
            sCu[(q * 4 + 2) * SBS + n] = w.z; sCu[(q * 4 + 3) * SBS + n] = w.w;
        }
        // stage delta / u: 64 d x 32 l
#pragma unroll
        for (int t = 0; t < 2; t++) {
            int f4 = tid + 256 * t;
            int dd = f4 >> 3, q = f4 & 7;
            *(float4*)&sDe[dd * SDS + q * 4] =
                *(const float4*)(de + (size_t)(d0 + dd) * LSEQ + l0 + q * 4);
            *(float4*)&sU[dd * SDS + q * 4] =
                *(const float4*)(ub + (size_t)(d0 + dd) * LSEQ + l0 + q * 4);
        }
        __syncthreads();

#pragma unroll
        for (int ph = 0; ph < 2; ph++) {
            const int lb0 = ph * 16;
#pragma unroll 4
            for (int li = 0; li < 16; li++) {
                const int l = lb0 + li;
                ulonglong2 bu2 = *(const ulonglong2*)&sBu[l * SBS + n0];
                ulonglong2 cu2 = *(const ulonglong2*)&sCu[l * SBS + n0];
#pragma unroll
                for (int k = 0; k < 4; k++) {
                    const int dd = dl + 16 * k;
                    float ds = sDe[dd * SDS + l];
                    float us = sU[dd * SDS + l];
                    float du = ds * us;
                    if (wantG) {
                        g[k] *= ds;
                        if (c == 0) sG[dd * SDS + l] = g[k];
                    }
                    uint64_t d2  = dup2(ds);
                    uint64_t du2 = dup2(du);
                    uint64_t dA0 = mul2(d2, A2[0]);
                    uint64_t dA1 = mul2(d2, A2[1]);
                    h[k][0] = fma2(dA0, h[k][0], mul2(du2, bu2.x));
                    h[k][1] = fma2(dA1, h[k][1], mul2(du2, bu2.y));
                    uint64_t y2 = fma2(cu2.y, h[k][1], mul2(cu2.x, h[k][0]));
                    float2 yf = u64_f2(y2);
                    sYp[li * 1024 + dd * 16 + c] = yf.x + yf.y;
                }
            }
            __syncthreads();

            // writeback 16 l x 64 d: thread (dd = tid>>2, qq = tid&3) -> float4
            {
                int dd = tid >> 2, qq = tid & 3;
                int lw = lb0 + qq * 4;
                float4 uv = *(const float4*)&sU[dd * SDS + lw];
                float4 o;
#pragma unroll
                for (int i = 0; i < 4; i++) {
                    int li = qq * 4 + i;
                    const float4* pp = (const float4*)&sYp[li * 1024 + dd * 16];
                    float4 p0 = pp[0], p1 = pp[1], p2 = pp[2], p3 = pp[3];
                    (&o.x)[i] = (((p0.x + p0.y) + (p0.z + p0.w)) +
                                 ((p1.x + p1.y) + (p1.z + p1.w))) +
                                (((p2.x + p2.y) + (p2.z + p2.w)) +
                                 ((p3.x + p3.y) + (p3.z + p3.w)));
                }
                o.x += uv.x * Ddw; o.y += uv.y * Ddw;
                o.z += uv.z * Ddw; o.w += uv.w * Ddw;
                *(float4*)(y + ((size_t)b * DMODEL + d0 + dd) * LSEQ + l0 + lw) = o;
            }
            __syncthreads();
        }

        // write gc tile (chunks 1..3)
        if (wantG) {
#pragma unroll
            for (int t = 0; t < 2; t++) {
                int f4 = tid + 256 * t;
                int dd = f4 >> 3, q = f4 & 7;
                float4 gv = *(const float4*)&sG[dd * SDS + q * 4];
                *(float4*)(g_G + ((size_t)b * DMODEL + d0 + dd) * LSEQ + l0 + q * 4) = gv;
            }
        }
    }

    if (wantH) {
        float* hp = g_H + (((size_t)b * NCH + chunk) * DMODEL + d0) * NSTATE;
#pragma unroll
        for (int k = 0; k < 4; k++) {
            int dd = dl + 16 * k;
            float2 v0 = u64_f2(h[k][0]);
            float2 v1 = u64_f2(h[k][1]);
            float4 hv = {v0.x, v0.y, v1.x, v1.y};
            *(float4*)(hp + dd * NSTATE + n0) = hv;
        }
    }
}

// ---------------- kernel 2b: chain hstarts across chunk boundaries ----------------
__global__ __launch_bounds__(256) void combine_kernel()
{
    int i = blockIdx.x * 256 + threadIdx.x;   // BATCH*DMODEL*NSTATE = 262144
    int b = i >> 16;
    int r = i & 65535;
    int d = r >> 6, n = r & 63;
    float Afull = g_P[n * APOWL + (CHL - 1)];  // A^CHL
    size_t dn = (size_t)d * NSTATE + n;
    size_t bb = (size_t)b * NCH;
    const float* gg = g_G + ((size_t)b * DMODEL + d) * LSEQ;

    float hs1 = g_H[(bb + 0) * DMODEL * NSTATE + dn];
    float E1  = gg[1 * CHL + (CHL - 1)] * Afull;
    float hs2 = E1 * hs1 + g_H[(bb + 1) * DMODEL * NSTATE + dn];
    float E2  = gg[2 * CHL + (CHL - 1)] * Afull;
    float hs3 = E2 * hs2 + g_H[(bb + 2) * DMODEL * NSTATE + dn];

    g_H2[(bb + 1) * DMODEL * NSTATE + dn] = hs1;
    g_H2[(bb + 2) * DMODEL * NSTATE + dn] = hs2;
    g_H2[(bb + 3) * DMODEL * NSTATE + dn] = hs3;
}

// ---------------- kernel 3: per-chunk correction (chunks 1..3) ----------------
// y[b,d,c*CHL+r] += g_G[b,d,c*CHL+r] * sum_n Cu[n,c*CHL+r] * A_n^(r+1) * hstart_c[b,d,n]
#define CD 128
#define CL 128
#define HSTR 68
#define VSTR 132
#define SMEM_CORR ((CD * HSTR + NSTATE * VSTR) * 4)   // 68608

__global__ __launch_bounds__(256) void corr_kernel(float* __restrict__ y)
{
    extern __shared__ __align__(16) float cs[];
    float* Hs = cs;                  // [CD][HSTR]
    float* Vs = cs + CD * HSTR;      // [NSTATE][VSTR]

    const int bz  = blockIdx.z;            // BATCH * 3
    const int b   = bz / 3;
    const int cc  = (bz % 3) + 1;          // chunk 1..3
    const int dd0 = blockIdx.y * CD;
    const int ll0 = blockIdx.x * CL;       // rel within chunk [0, CHL)
    const int labs = cc * CHL + ll0;
    const int tid = threadIdx.x;
    const int tl  = tid & 15;
    const int td  = tid >> 4;

    const float* Hg = g_H2 + (((size_t)b * NCH + cc) * DMODEL + dd0) * NSTATE;
    for (int i = tid; i < (CD * NSTATE) / 4; i += 256) {
        int dd = i >> 4, nn4 = (i & 15) * 4;
        *(float4*)&Hs[dd * HSTR + nn4] = *(const float4*)(Hg + dd * NSTATE + nn4);
    }
    const float* CuG = g_S + (size_t)b * MROWS * LSEQ + (size_t)1088 * LSEQ + labs;
    for (int i = tid; i < (NSTATE * CL) / 4; i += 256) {
        int nn = i >> 5, ll4 = (i & 31) * 4;
        float4 cu = *(const float4*)(CuG + (size_t)nn * LSEQ + ll4);
        float4 ap = *(const float4*)(g_P + nn * APOWL + ll0 + ll4);
        float4 v = {cu.x * ap.x, cu.y * ap.y, cu.z * ap.z, cu.w * ap.w};
        *(float4*)&Vs[nn * VSTR + ll4] = v;
    }
    __syncthreads();

    uint64_t acc[8][4];
#pragma unroll
    for (int i = 0; i < 8; i++)
#pragma unroll
        for (int j = 0; j < 4; j++) acc[i][j] = 0ull;

#pragma unroll 8
    for (int k = 0; k < NSTATE; k++) {
        ulonglong2 b0 = *(const ulonglong2*)&Vs[k * VSTR + tl * 8];
        ulonglong2 b1 = *(const ulonglong2*)&Vs[k * VSTR + tl * 8 + 4];
#pragma unroll
        for (int i = 0; i < 8; i++) {
            uint64_t ai = dup2(Hs[(td * 8 + i) * HSTR + k]);
            acc[i][0] = fma2(ai, b0.x, acc[i][0]);
            acc[i][1] = fma2(ai, b0.y, acc[i][1]);
            acc[i][2] = fma2(ai, b1.x, acc[i][2]);
            acc[i][3] = fma2(ai, b1.y, acc[i][3]);
        }
    }

#pragma unroll
    for (int i = 0; i < 8; i++) {
        int d = dd0 + td * 8 + i;
        const float* gp = g_G + ((size_t)b * DMODEL + d) * LSEQ + labs + tl * 8;
        float* yp = y + ((size_t)b * DMODEL + d) * LSEQ + labs + tl * 8;
        float4 g0 = *(const float4*)gp;
        float4 g1 = *(const float4*)(gp + 4);
        float4 y0 = *(const float4*)yp;
        float4 y1 = *(const float4*)(yp + 4);
        float2 a0 = u64_f2(acc[i][0]), a1 = u64_f2(acc[i][1]);
        float2 a2 = u64_f2(acc[i][2]), a3 = u64_f2(acc[i][3]);
        y0.x += g0.x * a0.x; y0.y += g0.y * a0.y;
        y0.z += g0.z * a1.x; y0.w += g0.w * a1.y;
        y1.x += g1.x * a2.x; y1.y += g1.y * a2.y;
        y1.z += g1.z * a3.x; y1.w += g1.w * a3.y;
        *(float4*)yp       = y0;
        *(float4*)(yp + 4) = y1;
    }
}

// ---------------- host launcher ----------------
extern "C" void kernel_launch(void* const* d_in, const int* in_sizes, int n_in,
                              void* d_out, int out_size)
{
    const float* u  = nullptr;
    const float* A  = nullptr;
    const float* Bm = nullptr;
    const float* Cm = nullptr;
    const float* D  = nullptr;
    const float* De = nullptr;
    for (int i = 0; i < n_in; i++) {
        int s = in_sizes[i];
        const float* p = (const float*)d_in[i];
        if      (s == 8388608 && !u)  u  = p;
        else if (s == 64      && !A)  A  = p;
        else if (s == 65536) { if (!Bm) Bm = p; else if (!Cm) Cm = p; }
        else if (s == 1024    && !D)  D  = p;
        else if (s == 1048576 && !De) De = p;
    }
    float* y = (float*)d_out;
    (void)out_size;

    cudaFuncSetAttribute(gemm_mma_kernel,
                         cudaFuncAttributeMaxDynamicSharedMemorySize, SMEM_G);
    cudaFuncSetAttribute(scan_q_kernel,
                         cudaFuncAttributeMaxDynamicSharedMemorySize, SMEM_SCAN);
    cudaFuncSetAttribute(corr_kernel,
                         cudaFuncAttributeMaxDynamicSharedMemorySize, SMEM_CORR);

    // 0) pack + round W; round u; A-power table
    pack_w_kernel<<<(MROWS * DMODEL + 255) / 256, 256>>>(De, Bm, Cm);
    round_u_kernel<<<(BATCH * DMODEL * LSEQ / 4 + 255) / 256, 256>>>(u);
    apow_kernel<<<(NSTATE * APOWL + 255) / 256, 256>>>(A);

    // 1) tf32 mma.sync GEMM: g_S[b] = W @ u[b]
    {
        dim3 grid(LSEQ / BN, MROWS / BM, BATCH);     // 16 x 9 x 4
        gemm_mma_kernel<<<grid, 256, SMEM_G>>>();
    }
    // 2) 4 chunks scanned in parallel (64 d per block, 4 d per thread)
    {
        dim3 grid(DMODEL / DT, BATCH, NCH);          // 16 x 4 x 4 = 256 blocks
        scan_q_kernel<<<grid, 256, SMEM_SCAN>>>(u, A, D, y);
    }
    // 2b) chain hstarts across the 3 boundaries
    combine_kernel<<<(BATCH * DMODEL * NSTATE) / 256, 256>>>();
    // 3) corrections for chunks 1..3
    {
        dim3 grid(CHL / CL, DMODEL / CD, BATCH * 3); // 4 x 8 x 12
        corr_kernel<<<grid, 256, SMEM_CORR>>>(y);
    }
}

// round 16
// speedup vs baseline: 1.3307x; 1.0074x over previous
#include <cuda_runtime.h>
#include <cstdint>

#define BATCH  4
#define DMODEL 1024
#define NSTATE 64
#define LSEQ   2048
#define NCH    4
#define CHL    (LSEQ / NCH)     // 512
#define MROWS  1152             // 1024 (Delta) + 64 (Bm) + 64 (Cm)
#define APOWL  1024

// ---------------- device scratch (allocation-free) ----------------
__device__ __align__(256) float g_W[MROWS * DMODEL];
__device__ __align__(256) float g_U[(size_t)BATCH * DMODEL * LSEQ];
__device__ __align__(256) float g_S[(size_t)BATCH * MROWS * LSEQ];
__device__ __align__(256) float g_G[(size_t)BATCH * DMODEL * LSEQ];    // within-chunk cumprod(delta)
__device__ __align__(256) float g_H [(size_t)BATCH * NCH * DMODEL * NSTATE]; // h* per chunk (end state)
__device__ __align__(256) float g_H2[(size_t)BATCH * NCH * DMODEL * NSTATE]; // hstart per chunk
__device__ __align__(256) float g_P[NSTATE * APOWL];                   // A_n^(m+1)

// ---------------- f32x2 packed helpers ----------------
__device__ __forceinline__ uint64_t dup2(float x) {
    uint64_t r; asm("mov.b64 %0, {%1, %1};" : "=l"(r) : "f"(x)); return r;
}
__device__ __forceinline__ uint64_t mul2(uint64_t a, uint64_t b) {
    uint64_t r; asm("mul.rn.f32x2 %0, %1, %2;" : "=l"(r) : "l"(a), "l"(b)); return r;
}
__device__ __forceinline__ uint64_t fma2(uint64_t a, uint64_t b, uint64_t c) {
    uint64_t r; asm("fma.rn.f32x2 %0, %1, %2, %3;" : "=l"(r) : "l"(a), "l"(b), "l"(c)); return r;
}
__device__ __forceinline__ float2 u64_f2(uint64_t v) {
    float2 f; asm("mov.b64 {%0, %1}, %2;" : "=f"(f.x), "=f"(f.y) : "l"(v)); return f;
}

// ---------------- tf32 helpers ----------------
__device__ __forceinline__ float tf32r(float x) {
    uint32_t r; asm("cvt.rna.tf32.f32 %0, %1;" : "=r"(r) : "f"(x));
    return __uint_as_float(r);
}
__device__ __forceinline__ void mma_tf32(float* c, const uint32_t* a, const uint32_t* b) {
    asm volatile("mma.sync.aligned.m16n8k8.row.col.f32.tf32.tf32.f32 "
        "{%0,%1,%2,%3}, {%4,%5,%6,%7}, {%8,%9}, {%0,%1,%2,%3};"
        : "+f"(c[0]), "+f"(c[1]), "+f"(c[2]), "+f"(c[3])
        : "r"(a[0]), "r"(a[1]), "r"(a[2]), "r"(a[3]), "r"(b[0]), "r"(b[1]));
}
__device__ __forceinline__ void cpasync16(uint32_t dst, const void* src) {
    asm volatile("cp.async.cg.shared.global [%0], [%1], 16;" :: "r"(dst), "l"(src) : "memory");
}
__device__ __forceinline__ uint32_t smem_u32(const void* p) {
    uint32_t a;
    asm("{ .reg .u64 t; cvta.to.shared.u64 t, %1; cvt.u32.u64 %0, t; }" : "=r"(a) : "l"(p));
    return a;
}
#define CP_COMMIT() asm volatile("cp.async.commit_group;" ::: "memory")

// ---------------- kernel 0: pack + tf32-round W ----------------
__global__ __launch_bounds__(256) void pack_w_kernel(
    const float* __restrict__ Delta, const float* __restrict__ Bm, const float* __restrict__ Cm)
{
    int i = blockIdx.x * 256 + threadIdx.x;
    if (i >= MROWS * DMODEL) return;
    int r = i >> 10, c = i & 1023;
    float v;
    if (r < 1024)      v = Delta[r * DMODEL + c];
    else if (r < 1088) v = Bm[(r - 1024) * DMODEL + c];
    else               v = Cm[(r - 1088) * DMODEL + c];
    g_W[i] = tf32r(v);
}

// ---------------- kernel 0b: tf32-round u ----------------
__global__ __launch_bounds__(256) void round_u_kernel(const float* __restrict__ u)
{
    size_t i = (size_t)blockIdx.x * 256 + threadIdx.x;
    float4 v = ((const float4*)u)[i];
    v.x = tf32r(v.x); v.y = tf32r(v.y); v.z = tf32r(v.z); v.w = tf32r(v.w);
    ((float4*)g_U)[i] = v;
}

// ---------------- kernel 0c: A-power table  g_P[n][m] = min(A_n^(m+1), 1e30) ----------------
__global__ __launch_bounds__(256) void apow_kernel(const float* __restrict__ A)
{
    int i = blockIdx.x * 256 + threadIdx.x;
    int n = i >> 10, m = i & 1023;
    float lg = log2f(A[n]);
    float v  = exp2f((float)(m + 1) * lg);
    g_P[n * APOWL + m] = fminf(v, 1e30f);
}

// ---------------- kernel 1: tf32 mma.sync GEMM, 3-stage cp.async pipeline ----------------
#define BM 128
#define BN 128
#define BK 32
#define ASTR 36
#define BSTR 136
#define AF (BM * ASTR)
#define BF (BK * BSTR)
#define STF (AF + BF)            // 8960 floats / stage
#define STGB (STF * 4)           // 35840 B
#define SMEM_G (3 * STGB)        // 107520 B -> 2 CTAs/SM
#define NCHUNK_G (DMODEL / BK)   // 32

__device__ __forceinline__ void load_chunk_g(int tid, int c, int m0, int n0,
                                             const float* __restrict__ Ub,
                                             uint32_t aSm, uint32_t bSm)
{
    const float* Wt = g_W + (size_t)m0 * DMODEL + c * BK;
#pragma unroll
    for (int i = 0; i < 4; i++) {
        int t = tid + 256 * i;
        int r = t >> 3, j = t & 7;
        cpasync16(aSm + r * (ASTR * 4) + j * 16, Wt + (size_t)r * DMODEL + j * 4);
    }
    const float* Ut = Ub + (size_t)(c * BK) * LSEQ + n0;
#pragma unroll
    for (int i = 0; i < 4; i++) {
        int t = tid + 256 * i;
        int k = t >> 5, j = t & 31;
        cpasync16(bSm + k * (BSTR * 4) + j * 16, Ut + (size_t)k * LSEQ + j * 4);
    }
}

__global__ __launch_bounds__(256, 2) void gemm_mma_kernel()
{
    extern __shared__ __align__(16) float sm[];
    const int tid  = threadIdx.x;
    const int wid  = tid >> 5, lane = tid & 31;
    const int wm   = wid & 3, wn = wid >> 2;
    const int g    = lane >> 2, tg = lane & 3;

    const int b  = blockIdx.z;
    const int m0 = blockIdx.y * BM;
    const int n0 = blockIdx.x * BN;
    const float* __restrict__ Ub = g_U + (size_t)b * DMODEL * LSEQ;
    float* __restrict__ Cb = g_S + (size_t)b * MROWS * LSEQ;

    const uint32_t sb = smem_u32(sm);

    float acc[2][8][4];
#pragma unroll
    for (int mt = 0; mt < 2; mt++)
#pragma unroll
        for (int nt = 0; nt < 8; nt++)
#pragma unroll
            for (int q = 0; q < 4; q++) acc[mt][nt][q] = 0.f;

    load_chunk_g(tid, 0, m0, n0, Ub, sb + 0 * STGB, sb + 0 * STGB + AF * 4);
    CP_COMMIT();
    load_chunk_g(tid, 1, m0, n0, Ub, sb + 1 * STGB, sb + 1 * STGB + AF * 4);
    CP_COMMIT();

    int sc = 0;   // compute stage
    for (int c = 0; c < NCHUNK_G; c++) {
        if (c + 1 < NCHUNK_G) {
            asm volatile("cp.async.wait_group 1;" ::: "memory");
        } else {
            asm volatile("cp.async.wait_group 0;" ::: "memory");
        }
        __syncthreads();

        if (c + 2 < NCHUNK_G) {
            int sl = sc + 2; if (sl >= 3) sl -= 3;
            load_chunk_g(tid, c + 2, m0, n0, Ub, sb + sl * STGB, sb + sl * STGB + AF * 4);
            CP_COMMIT();
        }

        const uint32_t* As = (const uint32_t*)(sm + sc * STF);
        const uint32_t* Bs = As + AF;
#pragma unroll
        for (int ks = 0; ks < 4; ks++) {
            const int k0 = ks * 8;
            uint32_t af[2][4];
#pragma unroll
            for (int mt = 0; mt < 2; mt++) {
                int row = wm * 32 + mt * 16;
                af[mt][0] = As[(row + g)     * ASTR + k0 + tg];
                af[mt][1] = As[(row + g + 8) * ASTR + k0 + tg];
                af[mt][2] = As[(row + g)     * ASTR + k0 + tg + 4];
                af[mt][3] = As[(row + g + 8) * ASTR + k0 + tg + 4];
            }
            uint32_t bf[8][2];
#pragma unroll
            for (int nt = 0; nt < 8; nt++) {
                int col = wn * 64 + nt * 8 + g;
                bf[nt][0] = Bs[(k0 + tg)     * BSTR + col];
                bf[nt][1] = Bs[(k0 + tg + 4) * BSTR + col];
            }
#pragma unroll
            for (int mt = 0; mt < 2; mt++)
#pragma unroll
                for (int nt = 0; nt < 8; nt++)
                    mma_tf32(acc[mt][nt], af[mt], bf[nt]);
        }
        if (++sc == 3) sc = 0;
    }

#pragma unroll
    for (int mt = 0; mt < 2; mt++) {
        int row0 = m0 + wm * 32 + mt * 16 + g;
#pragma unroll
        for (int nt = 0; nt < 8; nt++) {
            int col = n0 + wn * 64 + nt * 8 + 2 * tg;
            float2 v0 = {acc[mt][nt][0], acc[mt][nt][1]};
            float2 v1 = {acc[mt][nt][2], acc[mt][nt][3]};
            *(float2*)(Cb + (size_t)row0 * LSEQ + col)       = v0;
            *(float2*)(Cb + (size_t)(row0 + 8) * LSEQ + col) = v1;
        }
    }
}

// ---------------- kernel 2: quarter-scan, 128 d per block, 512 threads ----------------
// 512 thr = 32 dl x 16 c; thread owns n0=c*4 for d = d0+dl+{0,32,64,96}.
// Grid (8, 4, 4) = 128 blocks -> exactly 1 CTA/SM, single wave, 512 steps.
#define DT  128     // d per block
#define TL  32      // l per tile
#define SBS 68
#define SDS 36
// smem layout (floats)
#define OF_BU 0
#define OF_CU (OF_BU + TL * SBS)             // 2176
#define OF_DE (OF_CU + TL * SBS)             // 4352
#define OF_U  (OF_DE + DT * SDS)             // 8960
#define OF_G  (OF_U  + DT * SDS)             // 13568
#define OF_YP (OF_G  + DT * SDS)             // 18176
#define SCAN_FLOATS (OF_YP + 16 * 2048)      // 50944
#define SMEM_SCAN (SCAN_FLOATS * 4)          // 203776 bytes -> 1 CTA/SM

__global__ __launch_bounds__(512, 1) void scan_q_kernel(
    const float* __restrict__ u, const float* __restrict__ A,
    const float* __restrict__ Dv, float* __restrict__ y)
{
    extern __shared__ __align__(16) float sw[];
    float* sBu = sw + OF_BU;
    float* sCu = sw + OF_CU;
    float* sDe = sw + OF_DE;
    float* sU  = sw + OF_U;
    float* sG  = sw + OF_G;
    float* sYp = sw + OF_YP;    // [16 l][2048 = 128 d x 16 c]

    const int b     = blockIdx.y;
    const int d0    = blockIdx.x * DT;
    const int chunk = blockIdx.z;
    const int lbase = chunk * CHL;
    const bool wantG = (chunk > 0);
    const bool wantH = (chunk < NCH - 1);

    const float* __restrict__ de = g_S + (size_t)b * MROWS * LSEQ;
    const float* __restrict__ Bu = de + (size_t)1024 * LSEQ;
    const float* __restrict__ Cu = de + (size_t)1088 * LSEQ;
    const float* __restrict__ ub = u + (size_t)b * DMODEL * LSEQ;

    const int tid = threadIdx.x;
    const int dl  = tid >> 4;    // 0..31
    const int c   = tid & 15;    // 0..15
    const int n0  = c * 4;

    uint64_t A2[2];
#pragma unroll
    for (int p = 0; p < 2; p++)
        A2[p] = *(const uint64_t*)&A[n0 + 2 * p];

    const float Ddw = Dv[d0 + (tid >> 2)];   // writeback role: dd = tid>>2

    uint64_t h[4][2];
#pragma unroll
    for (int k = 0; k < 4; k++) { h[k][0] = 0ull; h[k][1] = 0ull; }
    float g[4] = {1.f, 1.f, 1.f, 1.f};

    for (int lt = 0; lt < CHL; lt += TL) {
        const int l0 = lbase + lt;
        __syncthreads();

        // stage Bu/Cu: 64 n x 32 l -> [l][n]  (512 float4 tasks = 1 pass)
        {
            int n = tid >> 3, q = tid & 7;
            float4 v = *(const float4*)(Bu + (size_t)n * LSEQ + l0 + q * 4);
            sBu[(q * 4 + 0) * SBS + n] = v.x; sBu[(q * 4 + 1) * SBS + n] = v.y;
            sBu[(q * 4 + 2) * SBS + n] = v.z; sBu[(q * 4 + 3) * SBS + n] = v.w;
            float4 w = *(const float4*)(Cu + (size_t)n * LSEQ + l0 + q * 4);
            sCu[(q * 4 + 0) * SBS + n] = w.x; sCu[(q * 4 + 1) * SBS + n] = w.y;
            sCu[(q * 4 + 2) * SBS + n] = w.z; sCu[(q * 4 + 3) * SBS + n] = w.w;
        }
        // stage delta / u: 128 d x 32 l (1024 float4 tasks = 2 passes)
#pragma unroll
        for (int t = 0; t < 2; t++) {
            int f4 = tid + 512 * t;
            int dd = f4 >> 3, q = f4 & 7;
            *(float4*)&sDe[dd * SDS + q * 4] =
                *(const float4*)(de + (size_t)(d0 + dd) * LSEQ + l0 + q * 4);
            *(float4*)&sU[dd * SDS + q * 4] =
                *(const float4*)(ub + (size_t)(d0 + dd) * LSEQ + l0 + q * 4);
        }
        __syncthreads();

#pragma unroll
        for (int ph = 0; ph < 2; ph++) {
            const int lb0 = ph * 16;
#pragma unroll 4
            for (int li = 0; li < 16; li++) {
                const int l = lb0 + li;
                ulonglong2 bu2 = *(const ulonglong2*)&sBu[l * SBS + n0];
                ulonglong2 cu2 = *(const ulonglong2*)&sCu[l * SBS + n0];
#pragma unroll
                for (int k = 0; k < 4; k++) {
                    const int dd = dl + 32 * k;
                    float ds = sDe[dd * SDS + l];
                    float us = sU[dd * SDS + l];
                    float du = ds * us;
                    if (wantG) {
                        g[k] *= ds;
                        if (c == 0) sG[dd * SDS + l] = g[k];
                    }
                    uint64_t d2  = dup2(ds);
                    uint64_t du2 = dup2(du);
                    uint64_t dA0 = mul2(d2, A2[0]);
                    uint64_t dA1 = mul2(d2, A2[1]);
                    h[k][0] = fma2(dA0, h[k][0], mul2(du2, bu2.x));
                    h[k][1] = fma2(dA1, h[k][1], mul2(du2, bu2.y));
                    uint64_t y2 = fma2(cu2.y, h[k][1], mul2(cu2.x, h[k][0]));
                    float2 yf = u64_f2(y2);
                    sYp[li * 2048 + dd * 16 + c] = yf.x + yf.y;
                }
            }
            __syncthreads();

            // writeback 16 l x 128 d: thread (dd = tid>>2, qq = tid&3) -> float4
            {
                int dd = tid >> 2, qq = tid & 3;
                int lw = lb0 + qq * 4;
                float4 uv = *(const float4*)&sU[dd * SDS + lw];
                float4 o;
#pragma unroll
                for (int i = 0; i < 4; i++) {
                    int li = qq * 4 + i;
                    const float4* pp = (const float4*)&sYp[li * 2048 + dd * 16];
                    float4 p0 = pp[0], p1 = pp[1], p2 = pp[2], p3 = pp[3];
                    (&o.x)[i] = (((p0.x + p0.y) + (p0.z + p0.w)) +
                                 ((p1.x + p1.y) + (p1.z + p1.w))) +
                                (((p2.x + p2.y) + (p2.z + p2.w)) +
                                 ((p3.x + p3.y) + (p3.z + p3.w)));
                }
                o.x += uv.x * Ddw; o.y += uv.y * Ddw;
                o.z += uv.z * Ddw; o.w += uv.w * Ddw;
                *(float4*)(y + ((size_t)b * DMODEL + d0 + dd) * LSEQ + l0 + lw) = o;
            }
            __syncthreads();
        }

        // write g tile (chunks 1..3)
        if (wantG) {
#pragma unroll
            for (int t = 0; t < 2; t++) {
                int f4 = tid + 512 * t;
                int dd = f4 >> 3, q = f4 & 7;
                float4 gv = *(const float4*)&sG[dd * SDS + q * 4];
                *(float4*)(g_G + ((size_t)b * DMODEL + d0 + dd) * LSEQ + l0 + q * 4) = gv;
            }
        }
    }

    if (wantH) {
        float* hp = g_H + (((size_t)b * NCH + chunk) * DMODEL + d0) * NSTATE;
#pragma unroll
        for (int k = 0; k < 4; k++) {
            int dd = dl + 32 * k;
            float2 v0 = u64_f2(h[k][0]);
            float2 v1 = u64_f2(h[k][1]);
            float4 hv = {v0.x, v0.y, v1.x, v1.y};
            *(float4*)(hp + dd * NSTATE + n0) = hv;
        }
    }
}

// ---------------- kernel 2b: chain hstarts across chunk boundaries ----------------
__global__ __launch_bounds__(256) void combine_kernel()
{
    int i = blockIdx.x * 256 + threadIdx.x;   // BATCH*DMODEL*NSTATE
    int b = i >> 16;
    int r = i & 65535;
    int d = r >> 6, n = r & 63;
    float Afull = g_P[n * APOWL + (CHL - 1)];  // A^CHL
    size_t dn = (size_t)d * NSTATE + n;
    size_t bb = (size_t)b * NCH;
    const float* gg = g_G + ((size_t)b * DMODEL + d) * LSEQ;

    float hs1 = g_H[(bb + 0) * DMODEL * NSTATE + dn];
    float E1  = gg[1 * CHL + (CHL - 1)] * Afull;
    float hs2 = E1 * hs1 + g_H[(bb + 1) * DMODEL * NSTATE + dn];
    float E2  = gg[2 * CHL + (CHL - 1)] * Afull;
    float hs3 = E2 * hs2 + g_H[(bb + 2) * DMODEL * NSTATE + dn];

    g_H2[(bb + 1) * DMODEL * NSTATE + dn] = hs1;
    g_H2[(bb + 2) * DMODEL * NSTATE + dn] = hs2;
    g_H2[(bb + 3) * DMODEL * NSTATE + dn] = hs3;
}

// ---------------- kernel 3: per-chunk correction (chunks 1..3) ----------------
#define CD 128
#define CL 128
#define HSTR 68
#define VSTR 132
#define SMEM_CORR ((CD * HSTR + NSTATE * VSTR) * 4)   // 68608

__global__ __launch_bounds__(256) void corr_kernel(float* __restrict__ y)
{
    extern __shared__ __align__(16) float cs[];
    float* Hs = cs;                  // [CD][HSTR]
    float* Vs = cs + CD * HSTR;      // [NSTATE][VSTR]

    const int bz  = blockIdx.z;            // BATCH * 3
    const int b   = bz / 3;
    const int cc  = (bz % 3) + 1;          // chunk 1..3
    const int dd0 = blockIdx.y * CD;
    const int ll0 = blockIdx.x * CL;
    const int labs = cc * CHL + ll0;
    const int tid = threadIdx.x;
    const int tl  = tid & 15;
    const int td  = tid >> 4;

    const float* Hg = g_H2 + (((size_t)b * NCH + cc) * DMODEL + dd0) * NSTATE;
    for (int i = tid; i < (CD * NSTATE) / 4; i += 256) {
        int dd = i >> 4, nn4 = (i & 15) * 4;
        *(float4*)&Hs[dd * HSTR + nn4] = *(const float4*)(Hg + dd * NSTATE + nn4);
    }
    const float* CuG = g_S + (size_t)b * MROWS * LSEQ + (size_t)1088 * LSEQ + labs;
    for (int i = tid; i < (NSTATE * CL) / 4; i += 256) {
        int nn = i >> 5, ll4 = (i & 31) * 4;
        float4 cu = *(const float4*)(CuG + (size_t)nn * LSEQ + ll4);
        float4 ap = *(const float4*)(g_P + nn * APOWL + ll0 + ll4);
        float4 v = {cu.x * ap.x, cu.y * ap.y, cu.z * ap.z, cu.w * ap.w};
        *(float4*)&Vs[nn * VSTR + ll4] = v;
    }
    __syncthreads();

    uint64_t acc[8][4];
#pragma unroll
    for (int i = 0; i < 8; i++)
#pragma unroll
        for (int j = 0; j < 4; j++) acc[i][j] = 0ull;

#pragma unroll 8
    for (int k = 0; k < NSTATE; k++) {
        ulonglong2 b0 = *(const ulonglong2*)&Vs[k * VSTR + tl * 8];
        ulonglong2 b1 = *(const ulonglong2*)&Vs[k * VSTR + tl * 8 + 4];
#pragma unroll
        for (int i = 0; i < 8; i++) {
            uint64_t ai = dup2(Hs[(td * 8 + i) * HSTR + k]);
            acc[i][0] = fma2(ai, b0.x, acc[i][0]);
            acc[i][1] = fma2(ai, b0.y, acc[i][1]);
            acc[i][2] = fma2(ai, b1.x, acc[i][2]);
            acc[i][3] = fma2(ai, b1.y, acc[i][3]);
        }
    }

#pragma unroll
    for (int i = 0; i < 8; i++) {
        int d = dd0 + td * 8 + i;
        const float* gp = g_G + ((size_t)b * DMODEL + d) * LSEQ + labs + tl * 8;
        float* yp = y + ((size_t)b * DMODEL + d) * LSEQ + labs + tl * 8;
        float4 g0 = *(const float4*)gp;
        float4 g1 = *(const float4*)(gp + 4);
        float4 y0 = *(const float4*)yp;
        float4 y1 = *(const float4*)(yp + 4);
        float2 a0 = u64_f2(acc[i][0]), a1 = u64_f2(acc[i][1]);
        float2 a2 = u64_f2(acc[i][2]), a3 = u64_f2(acc[i][3]);
        y0.x += g0.x * a0.x; y0.y += g0.y * a0.y;
        y0.z += g0.z * a1.x; y0.w += g0.w * a1.y;
        y1.x += g1.x * a2.x; y1.y += g1.y * a2.y;
        y1.z += g1.z * a3.x; y1.w += g1.w * a3.y;
        *(float4*)yp       = y0;
        *(float4*)(yp + 4) = y1;
    }
}

// ---------------- host launcher ----------------
extern "C" void kernel_launch(void* const* d_in, const int* in_sizes, int n_in,
                              void* d_out, int out_size)
{
    const float* u  = nullptr;
    const float* A  = nullptr;
    const float* Bm = nullptr;
    const float* Cm = nullptr;
    const float* D  = nullptr;
    const float* De = nullptr;
    for (int i = 0; i < n_in; i++) {
        int s = in_sizes[i];
        const float* p = (const float*)d_in[i];
        if      (s == 8388608 && !u)  u  = p;
        else if (s == 64      && !A)  A  = p;
        else if (s == 65536) { if (!Bm) Bm = p; else if (!Cm) Cm = p; }
        else if (s == 1024    && !D)  D  = p;
        else if (s == 1048576 && !De) De = p;
    }
    float* y = (float*)d_out;
    (void)out_size;

    cudaFuncSetAttribute(gemm_mma_kernel,
                         cudaFuncAttributeMaxDynamicSharedMemorySize, SMEM_G);
    cudaFuncSetAttribute(scan_q_kernel,
                         cudaFuncAttributeMaxDynamicSharedMemorySize, SMEM_SCAN);
    cudaFuncSetAttribute(corr_kernel,
                         cudaFuncAttributeMaxDynamicSharedMemorySize, SMEM_CORR);

    // 0) pack + round W; round u; A-power table
    pack_w_kernel<<<(MROWS * DMODEL + 255) / 256, 256>>>(De, Bm, Cm);
    round_u_kernel<<<(BATCH * DMODEL * LSEQ / 4 + 255) / 256, 256>>>(u);
    apow_kernel<<<(NSTATE * APOWL + 255) / 256, 256>>>(A);

    // 1) tf32 mma.sync GEMM (3-stage pipeline): g_S[b] = W @ u[b]
    {
        dim3 grid(LSEQ / BN, MROWS / BM, BATCH);     // 16 x 9 x 4
        gemm_mma_kernel<<<grid, 256, SMEM_G>>>();
    }
    // 2) 4 chunks scanned in parallel (128 d per block, 1 CTA/SM, single wave)
    {
        dim3 grid(DMODEL / DT, BATCH, NCH);          // 8 x 4 x 4 = 128 blocks
        scan_q_kernel<<<grid, 512, SMEM_SCAN>>>(u, A, D, y);
    }
    // 2b) chain hstarts across the 3 boundaries
    combine_kernel<<<(BATCH * DMODEL * NSTATE) / 256, 256>>>();
    // 3) corrections for chunks 1..3
    {
        dim3 grid(CHL / CL, DMODEL / CD, BATCH * 3); // 4 x 8 x 12
        corr_kernel<<<grid, 256, SMEM_CORR>>>(y);
    }
}